// round 15
// baseline (speedup 1.0000x reference)
#include <cuda_runtime.h>
#include <cuda_fp16.h>
#include <cstdint>

#define Bq   8
#define Nq   2048
#define DIN  128
#define DOUT 64
#define PIT  132    // fp32 smem pitch (k_prep proj role)
#define PITH 136    // half smem pitch (k_gat)
#define PXH  136    // half pitch for xp staging

__device__ __half    g_xpT[Bq * DOUT * Nq];   // projected features, half, [b][d][n]
__device__ float     g_es[Bq * Nq];
__device__ float     g_ed[Bq * Nq];
__device__ uint32_t  g_adjb[Bq * Nq * 64];    // adj bitmask: 2048 bits per row

static __device__ __forceinline__ float to_tf32(float x) {
    uint32_t r;
    asm("cvt.rna.tf32.f32 %0, %1;" : "=r"(r) : "f"(x));
    return __uint_as_float(r);
}

// tf32: D += A(16x8) * B(8x8)
static __device__ __forceinline__ void mma8(float* c, const uint32_t* a,
                                            uint32_t b0, uint32_t b1) {
    asm volatile(
        "mma.sync.aligned.m16n8k8.row.col.f32.tf32.tf32.f32 "
        "{%0,%1,%2,%3}, {%4,%5,%6,%7}, {%8,%9}, {%0,%1,%2,%3};"
        : "+f"(c[0]), "+f"(c[1]), "+f"(c[2]), "+f"(c[3])
        : "r"(a[0]), "r"(a[1]), "r"(a[2]), "r"(a[3]), "r"(b0), "r"(b1));
}
// fp16: D += A(16x16) * B(16x8), fp32 accum
static __device__ __forceinline__ void mma16(float* c, const uint32_t* a,
                                             uint32_t b0, uint32_t b1) {
    asm volatile(
        "mma.sync.aligned.m16n8k16.row.col.f32.f16.f16.f32 "
        "{%0,%1,%2,%3}, {%4,%5,%6,%7}, {%8,%9}, {%0,%1,%2,%3};"
        : "+f"(c[0]), "+f"(c[1]), "+f"(c[2]), "+f"(c[3])
        : "r"(a[0]), "r"(a[1]), "r"(a[2]), "r"(a[3]), "r"(b0), "r"(b1));
}

#define BAR_SYNC(id)   asm volatile("bar.sync %0, 512;"   :: "r"(id) : "memory")
#define BAR_ARRIVE(id) asm volatile("bar.arrive %0, 512;" :: "r"(id) : "memory")

// ---------------------------------------------------------------------------
// Kernel 1 (fused prep): blocks 0-127 = xp projection (tf32 MMA, es/ed,
// coalesced half transposed store). Blocks 128+ = adj bitmask pack: one warp
// per adjacency row, 32 batched LDG.32 -> ballot -> coalesced STG.
// ---------------------------------------------------------------------------
#define PJ_AS   0
#define PJ_WS   (128 * PIT)
#define PJ_BS   (PJ_WS + 64 * PIT)
#define PJ_ASR  (PJ_BS + 64)
#define PJ_ADR  (PJ_ASR + 64)
#define PJ_ESH  (PJ_ADR + 64)
#define PJ_EDH  (PJ_ESH + 256)
#define PJ_XPH  (PJ_EDH + 256)
#define PJ_SIZE ((PJ_XPH + 32 * PXH) * 4)

__global__ void __launch_bounds__(256, 1)
k_prep(const float* __restrict__ x, const int* __restrict__ adj,
       const float* __restrict__ W, const float* __restrict__ bvec,
       const float* __restrict__ a) {
    int tid = threadIdx.x, wid = tid >> 5, lid = tid & 31;

    if (blockIdx.x >= 128) {
        // =================== PACK ROLE ===================
        int row = (blockIdx.x - 128) * 8 + wid;     // 0..16383
        const int* src = adj + (size_t)row * Nq;
        uint32_t* dst = g_adjb + (size_t)row * 64;
        #pragma unroll
        for (int h = 0; h < 2; h++) {
            uint32_t myword = 0;
            #pragma unroll
            for (int i = 0; i < 32; i++) {
                int v = src[h * 1024 + i * 32 + lid];
                uint32_t bal = __ballot_sync(0xffffffffu, v != 0);
                if (lid == i) myword = bal;
            }
            dst[h * 32 + lid] = myword;
        }
        return;
    }

    // =================== PROJ ROLE ===================
    extern __shared__ float sh[];
    float* AS  = sh + PJ_AS;
    float* WS  = sh + PJ_WS;
    float* bsh = sh + PJ_BS;
    float* asr = sh + PJ_ASR;
    float* adr = sh + PJ_ADR;
    float* esh = sh + PJ_ESH;
    float* edh = sh + PJ_EDH;
    __half* xph = (__half*)(sh + PJ_XPH);

    int g = lid >> 2, tg = lid & 3;
    int row0 = blockIdx.x << 7;

    {
        int r = tid & 127, half = tid >> 7;
        const float4* src = (const float4*)(x + (size_t)(row0 + r) * DIN + half * 64);
        float* dst = AS + r * PIT + half * 64;
        #pragma unroll
        for (int i = 0; i < 16; i++) {
            float4 v = src[i];
            v.x = to_tf32(v.x); v.y = to_tf32(v.y);
            v.z = to_tf32(v.z); v.w = to_tf32(v.w);
            ((float4*)dst)[i] = v;
        }
    }
    {
        int d = tid & 63, q = tid >> 6;
        const float4* src = (const float4*)(W + (size_t)d * DIN + q * 32);
        float* dst = WS + d * PIT + q * 32;
        #pragma unroll
        for (int i = 0; i < 8; i++) {
            float4 v = src[i];
            v.x = to_tf32(v.x); v.y = to_tf32(v.y);
            v.z = to_tf32(v.z); v.w = to_tf32(v.w);
            ((float4*)dst)[i] = v;
        }
    }
    if (tid < 64) {
        bsh[tid] = bvec[tid];
        asr[tid] = a[tid];
        adr[tid] = a[DOUT + tid];
    }
    __syncthreads();

    float acc[2][4][4];
    #pragma unroll
    for (int t = 0; t < 2; t++)
        #pragma unroll
        for (int j = 0; j < 4; j++)
            #pragma unroll
            for (int c = 0; c < 4; c++) acc[t][j][c] = 0.f;

    int gm = wid >> 1, h = wid & 1;
    const float* Abase = AS + (32 * gm + g) * PIT + tg;
    const float* Bbase = WS + (32 * h + g) * PIT + tg;

    #pragma unroll
    for (int ks = 0; ks < 16; ks++) {
        int kb = ks * 8;
        uint32_t A[2][4];
        #pragma unroll
        for (int t = 0; t < 2; t++) {
            const float* ap = Abase + t * 16 * PIT + kb;
            A[t][0] = __float_as_uint(ap[0]);
            A[t][1] = __float_as_uint(ap[8 * PIT]);
            A[t][2] = __float_as_uint(ap[4]);
            A[t][3] = __float_as_uint(ap[8 * PIT + 4]);
        }
        #pragma unroll
        for (int j = 0; j < 4; j++) {
            const float* bp = Bbase + j * 8 * PIT + kb;
            uint32_t B0 = __float_as_uint(bp[0]);
            uint32_t B1 = __float_as_uint(bp[4]);
            mma8(acc[0][j], A[0], B0, B1);
            mma8(acc[1][j], A[1], B0, B1);
        }
    }

    #pragma unroll
    for (int t = 0; t < 2; t++) {
        #pragma unroll
        for (int rw = 0; rw < 2; rw++) {
            int m = 32 * gm + g + 16 * t + 8 * rw;
            float es = 0.f, ed = 0.f;
            #pragma unroll
            for (int j = 0; j < 4; j++) {
                int d = 32 * h + 8 * j + 2 * tg;
                float f0 = acc[t][j][2 * rw]     + bsh[d];
                float f1 = acc[t][j][2 * rw + 1] + bsh[d + 1];
                es += f0 * asr[d] + f1 * asr[d + 1];
                ed += f0 * adr[d] + f1 * adr[d + 1];
                xph[(size_t)d * PXH + m]       = __float2half_rn(f0);
                xph[(size_t)(d + 1) * PXH + m] = __float2half_rn(f1);
            }
            es += __shfl_xor_sync(0xffffffffu, es, 1);
            es += __shfl_xor_sync(0xffffffffu, es, 2);
            ed += __shfl_xor_sync(0xffffffffu, ed, 1);
            ed += __shfl_xor_sync(0xffffffffu, ed, 2);
            if (tg == 0) { esh[h * 128 + m] = es; edh[h * 128 + m] = ed; }
        }
    }
    __syncthreads();
    {
        int b = row0 >> 11, nloc = row0 & (Nq - 1);
        int d = tid >> 2, c = tid & 3;
        const uint4* src = (const uint4*)(xph + (size_t)d * PXH + c * 32);
        uint4* dst = (uint4*)(g_xpT + ((size_t)b * DOUT + d) * Nq + nloc + c * 32);
        #pragma unroll
        for (int i = 0; i < 4; i++) dst[i] = src[i];
    }
    if (tid < 128) {
        g_es[row0 + tid] = esh[tid] + esh[128 + tid];
        g_ed[row0 + tid] = edh[tid] + edh[128 + tid];
    }
}

// ---------------------------------------------------------------------------
// Kernel 2: R8-config warp-specialized fp16 GAT attention, but adj comes from
// the packed bitmask (broadcast LDG.32 + nibble test) instead of int4 DRAM
// streams. Everything else byte-identical to the 45.6us R8 kernel.
// ---------------------------------------------------------------------------
#define GPS_STRIDE 34816                 // 128*PITH*2 bytes
#define GXT_STRIDE 17408                 // 64*PITH*2 bytes
#define GXT_BASE   (3 * GPS_STRIDE)
#define GE1_OFF    (GXT_BASE + 3 * GXT_STRIDE)
#define GEA_OFF    (GE1_OFF + 8192)
#define GS1_OFF    (GEA_OFF + 8192)
#define GSA_OFF    (GS1_OFF + 512)
#define GDS_OFF    (GSA_OFF + 512)
#define GA_SIZE    (GDS_OFF + 512)

__global__ void __launch_bounds__(512, 1)
k_gat(float* __restrict__ out) {
    extern __shared__ char smc[];
    float* E1n = (float*)(smc + GE1_OFF);
    float* Ean = (float*)(smc + GEA_OFF);
    float* Es1 = (float*)(smc + GS1_OFF);
    float* Esa = (float*)(smc + GSA_OFF);
    float* dsh = (float*)(smc + GDS_OFF);

    int tid = threadIdx.x, wid = tid >> 5, lid = tid & 31;
    int g = lid >> 2, tg = lid & 3;
    int b  = blockIdx.x >> 4;
    int m0 = (blockIdx.x & 15) << 7;

    // ---- exp tables (S = 1/256 folded into row tables) ----
    {
        const float* edb = g_ed + b * Nq;
        #pragma unroll
        for (int i = 0; i < 4; i++) {
            int n = tid + 512 * i;
            float v = edb[n];
            E1n[n] = __expf(v);
            Ean[n] = __expf(0.2f * v);
        }
        if (tid < 128) {
            float v = g_es[b * Nq + m0 + tid];
            Es1[tid] = __expf(v) * 0.00390625f;
            Esa[tid] = __expf(0.2f * v) * 0.00390625f;
        }
    }
    __syncthreads();

    if (wid >= 8) {
        // =================== PRODUCER ===================
        int p = wid - 8;
        const uint32_t* bmr = g_adjb + ((size_t)b * Nq + m0) * 64;
        const __half*   gxT = g_xpT + (size_t)b * DOUT * Nq;
        int widx = lid >> 3;             // word within tile (4 words per 128 n)
        int nsh  = (lid & 7) * 4;        // nibble shift
        float dsum[16];
        #pragma unroll
        for (int i = 0; i < 16; i++) dsum[i] = 0.f;

        for (int t = 0; t < 16; t++) {
            int n0 = t << 7;
            int buf = t % 3;
            __half* PS = (__half*)(smc + buf * GPS_STRIDE);
            __half* XT = (__half*)(smc + GXT_BASE + buf * GXT_STRIDE);

            if (t >= 3) BAR_SYNC(4 + buf);   // wait: consumers done with t-3

            // XT loads: warp-per-row (uint2 = 4 halves), coalesced 256B rows
            uint2 xtv[8];
            #pragma unroll
            for (int ps = 0; ps < 8; ps++) {
                int row = ps * 8 + p;
                xtv[ps] = ((const uint2*)(gxT + (size_t)row * Nq + n0))[lid];
            }

            float4 e1 = *(const float4*)(E1n + n0 + 4 * lid);
            float4 ea = *(const float4*)(Ean + n0 + 4 * lid);
            int wbase = (n0 >> 5) + widx;

            // P build from bitmask (scaled, half2-packed)
            #pragma unroll
            for (int it = 0; it < 16; it++) {
                int m = (it << 3) + p;
                uint32_t w = bmr[m * 64 + wbase];
                uint32_t nib = w >> nsh;
                float e1m = Es1[m], eam = Esa[m];
                float p0 = (nib & 1u) ? fmaxf(e1m * e1.x, eam * ea.x) : 0.f;
                float p1 = (nib & 2u) ? fmaxf(e1m * e1.y, eam * ea.y) : 0.f;
                float p2 = (nib & 4u) ? fmaxf(e1m * e1.z, eam * ea.z) : 0.f;
                float p3 = (nib & 8u) ? fmaxf(e1m * e1.w, eam * ea.w) : 0.f;
                __half2 h01 = __floats2half2_rn(p0, p1);
                __half2 h23 = __floats2half2_rn(p2, p3);
                float2 f01 = __half22float2(h01);
                float2 f23 = __half22float2(h23);
                dsum[it] += (f01.x + f01.y) + (f23.x + f23.y);
                uint2 pk;
                pk.x = *(uint32_t*)&h01;
                pk.y = *(uint32_t*)&h23;
                *(uint2*)(PS + (size_t)m * PITH + 4 * lid) = pk;
            }
            #pragma unroll
            for (int ps = 0; ps < 8; ps++) {
                int row = ps * 8 + p;
                *(uint2*)(XT + (size_t)row * PITH + 4 * lid) = xtv[ps];
            }
            BAR_ARRIVE(1 + buf);             // signal: tile t ready
        }

        #pragma unroll
        for (int it = 0; it < 16; it++) {
            float v = dsum[it];
            v += __shfl_xor_sync(0xffffffffu, v, 16);
            v += __shfl_xor_sync(0xffffffffu, v, 8);
            v += __shfl_xor_sync(0xffffffffu, v, 4);
            v += __shfl_xor_sync(0xffffffffu, v, 2);
            v += __shfl_xor_sync(0xffffffffu, v, 1);
            if (lid == 0) dsh[(it << 3) + p] = v;
        }
        __syncthreads();
    } else {
        // =================== CONSUMER ===================
        float acc[2][4][4];
        #pragma unroll
        for (int mt = 0; mt < 2; mt++)
            #pragma unroll
            for (int j = 0; j < 4; j++)
                #pragma unroll
                for (int c = 0; c < 4; c++) acc[mt][j][c] = 0.f;

        int gm = wid >> 1, dg = wid & 1;

        for (int t = 0; t < 16; t++) {
            int buf = t % 3;
            const __half* PS = (const __half*)(smc + buf * GPS_STRIDE);
            const __half* XT = (const __half*)(smc + GXT_BASE + buf * GXT_STRIDE);
            const __half* Abase = PS + (32 * gm + g) * PITH + 2 * tg;
            const __half* Bbase = XT + (32 * dg + g) * PITH + 2 * tg;

            BAR_SYNC(1 + buf);               // wait: tile t ready

            #pragma unroll
            for (int ks = 0; ks < 8; ks++) {
                int kb = ks * 16;
                uint32_t A[2][4];
                #pragma unroll
                for (int mt = 0; mt < 2; mt++) {
                    const __half* ap = Abase + mt * 16 * PITH + kb;
                    A[mt][0] = *(const uint32_t*)(ap);
                    A[mt][1] = *(const uint32_t*)(ap + 8 * PITH);
                    A[mt][2] = *(const uint32_t*)(ap + 8);
                    A[mt][3] = *(const uint32_t*)(ap + 8 * PITH + 8);
                }
                #pragma unroll
                for (int j = 0; j < 4; j++) {
                    const __half* bp = Bbase + j * 8 * PITH + kb;
                    uint32_t B0 = *(const uint32_t*)(bp);
                    uint32_t B1 = *(const uint32_t*)(bp + 8);
                    mma16(acc[0][j], A[0], B0, B1);
                    mma16(acc[1][j], A[1], B0, B1);
                }
            }
            if (t < 13) BAR_ARRIVE(4 + buf); // signal: buffer free
        }
        __syncthreads();

        // ---- normalize + write ----
        float* ob = out + ((size_t)b * Nq + m0) * DOUT;
        #pragma unroll
        for (int mt = 0; mt < 2; mt++) {
            #pragma unroll
            for (int rw = 0; rw < 2; rw++) {
                int m = 32 * gm + 16 * mt + g + 8 * rw;
                float inv = 1.0f / dsh[m];
                #pragma unroll
                for (int j = 0; j < 4; j++) {
                    float2 o = make_float2(acc[mt][j][2 * rw] * inv,
                                           acc[mt][j][2 * rw + 1] * inv);
                    *(float2*)(ob + (size_t)m * DOUT + 32 * dg + 8 * j + 2 * tg) = o;
                }
            }
        }
    }
}

// ---------------------------------------------------------------------------
extern "C" void kernel_launch(void* const* d_in, const int* in_sizes, int n_in,
                              void* d_out, int out_size) {
    const float* x    = (const float*)d_in[0];
    const int*   adj  = (const int*)d_in[1];
    const float* W    = (const float*)d_in[2];
    const float* bvec = (const float*)d_in[3];
    const float* a    = (const float*)d_in[4];
    float* out = (float*)d_out;

    cudaFuncSetAttribute(k_prep, cudaFuncAttributeMaxDynamicSharedMemorySize, PJ_SIZE);
    cudaFuncSetAttribute(k_gat,  cudaFuncAttributeMaxDynamicSharedMemorySize, GA_SIZE);

    k_prep<<<128 + Bq * Nq / 8, 256, PJ_SIZE>>>(x, adj, W, bvec, a);
    k_gat<<<Bq * (Nq / 128), 512, GA_SIZE>>>(out);
}

// round 16
// speedup vs baseline: 1.4674x; 1.4674x over previous
#include <cuda_runtime.h>
#include <cuda_fp16.h>
#include <cstdint>

#define Bq   8
#define Nq   2048
#define DIN  128
#define DOUT 64
#define PIT  132    // fp32 smem pitch (k_proj)
#define PITH 136    // half smem pitch (k_gat)
#define PXH  136    // half pitch for k_proj xp staging

__device__ __half g_xpT[Bq * DOUT * Nq];  // projected features, half, [b][d][n]
__device__ float  g_es[Bq * Nq];
__device__ float  g_ed[Bq * Nq];

static __device__ __forceinline__ float to_tf32(float x) {
    uint32_t r;
    asm("cvt.rna.tf32.f32 %0, %1;" : "=r"(r) : "f"(x));
    return __uint_as_float(r);
}

// tf32: D += A(16x8) * B(8x8)
static __device__ __forceinline__ void mma8(float* c, const uint32_t* a,
                                            uint32_t b0, uint32_t b1) {
    asm volatile(
        "mma.sync.aligned.m16n8k8.row.col.f32.tf32.tf32.f32 "
        "{%0,%1,%2,%3}, {%4,%5,%6,%7}, {%8,%9}, {%0,%1,%2,%3};"
        : "+f"(c[0]), "+f"(c[1]), "+f"(c[2]), "+f"(c[3])
        : "r"(a[0]), "r"(a[1]), "r"(a[2]), "r"(a[3]), "r"(b0), "r"(b1));
}
// fp16: D += A(16x16) * B(16x8), fp32 accum
static __device__ __forceinline__ void mma16(float* c, const uint32_t* a,
                                             uint32_t b0, uint32_t b1) {
    asm volatile(
        "mma.sync.aligned.m16n8k16.row.col.f32.f16.f16.f32 "
        "{%0,%1,%2,%3}, {%4,%5,%6,%7}, {%8,%9}, {%0,%1,%2,%3};"
        : "+f"(c[0]), "+f"(c[1]), "+f"(c[2]), "+f"(c[3])
        : "r"(a[0]), "r"(a[1]), "r"(a[2]), "r"(a[3]), "r"(b0), "r"(b1));
}

#define BAR_SYNC(id)   asm volatile("bar.sync %0, 512;"   :: "r"(id) : "memory")
#define BAR_ARRIVE(id) asm volatile("bar.arrive %0, 512;" :: "r"(id) : "memory")

// ---------------------------------------------------------------------------
// Kernel 1: xp = x @ W^T + b via tf32 mma.sync (unchanged from R14).
// ---------------------------------------------------------------------------
#define PJ_AS   0
#define PJ_WS   (128 * PIT)
#define PJ_BS   (PJ_WS + 64 * PIT)
#define PJ_ASR  (PJ_BS + 64)
#define PJ_ADR  (PJ_ASR + 64)
#define PJ_ESH  (PJ_ADR + 64)
#define PJ_EDH  (PJ_ESH + 256)
#define PJ_XPH  (PJ_EDH + 256)
#define PJ_SIZE ((PJ_XPH + 32 * PXH) * 4)

__global__ void __launch_bounds__(256, 1)
k_proj(const float* __restrict__ x, const float* __restrict__ W,
       const float* __restrict__ bvec, const float* __restrict__ a) {
    extern __shared__ float sh[];
    float* AS  = sh + PJ_AS;
    float* WS  = sh + PJ_WS;
    float* bsh = sh + PJ_BS;
    float* asr = sh + PJ_ASR;
    float* adr = sh + PJ_ADR;
    float* esh = sh + PJ_ESH;
    float* edh = sh + PJ_EDH;
    __half* xph = (__half*)(sh + PJ_XPH);

    int tid = threadIdx.x, wid = tid >> 5, lid = tid & 31;
    int g = lid >> 2, tg = lid & 3;
    int row0 = blockIdx.x << 7;

    {
        int r = tid & 127, half = tid >> 7;
        const float4* src = (const float4*)(x + (size_t)(row0 + r) * DIN + half * 64);
        float* dst = AS + r * PIT + half * 64;
        #pragma unroll
        for (int i = 0; i < 16; i++) {
            float4 v = src[i];
            v.x = to_tf32(v.x); v.y = to_tf32(v.y);
            v.z = to_tf32(v.z); v.w = to_tf32(v.w);
            ((float4*)dst)[i] = v;
        }
    }
    {
        int d = tid & 63, q = tid >> 6;
        const float4* src = (const float4*)(W + (size_t)d * DIN + q * 32);
        float* dst = WS + d * PIT + q * 32;
        #pragma unroll
        for (int i = 0; i < 8; i++) {
            float4 v = src[i];
            v.x = to_tf32(v.x); v.y = to_tf32(v.y);
            v.z = to_tf32(v.z); v.w = to_tf32(v.w);
            ((float4*)dst)[i] = v;
        }
    }
    if (tid < 64) {
        bsh[tid] = bvec[tid];
        asr[tid] = a[tid];
        adr[tid] = a[DOUT + tid];
    }
    __syncthreads();

    float acc[2][4][4];
    #pragma unroll
    for (int t = 0; t < 2; t++)
        #pragma unroll
        for (int j = 0; j < 4; j++)
            #pragma unroll
            for (int c = 0; c < 4; c++) acc[t][j][c] = 0.f;

    int gm = wid >> 1, h = wid & 1;
    const float* Abase = AS + (32 * gm + g) * PIT + tg;
    const float* Bbase = WS + (32 * h + g) * PIT + tg;

    #pragma unroll
    for (int ks = 0; ks < 16; ks++) {
        int kb = ks * 8;
        uint32_t A[2][4];
        #pragma unroll
        for (int t = 0; t < 2; t++) {
            const float* ap = Abase + t * 16 * PIT + kb;
            A[t][0] = __float_as_uint(ap[0]);
            A[t][1] = __float_as_uint(ap[8 * PIT]);
            A[t][2] = __float_as_uint(ap[4]);
            A[t][3] = __float_as_uint(ap[8 * PIT + 4]);
        }
        #pragma unroll
        for (int j = 0; j < 4; j++) {
            const float* bp = Bbase + j * 8 * PIT + kb;
            uint32_t B0 = __float_as_uint(bp[0]);
            uint32_t B1 = __float_as_uint(bp[4]);
            mma8(acc[0][j], A[0], B0, B1);
            mma8(acc[1][j], A[1], B0, B1);
        }
    }

    #pragma unroll
    for (int t = 0; t < 2; t++) {
        #pragma unroll
        for (int rw = 0; rw < 2; rw++) {
            int m = 32 * gm + g + 16 * t + 8 * rw;
            float es = 0.f, ed = 0.f;
            #pragma unroll
            for (int j = 0; j < 4; j++) {
                int d = 32 * h + 8 * j + 2 * tg;
                float f0 = acc[t][j][2 * rw]     + bsh[d];
                float f1 = acc[t][j][2 * rw + 1] + bsh[d + 1];
                es += f0 * asr[d] + f1 * asr[d + 1];
                ed += f0 * adr[d] + f1 * adr[d + 1];
                xph[(size_t)d * PXH + m]       = __float2half_rn(f0);
                xph[(size_t)(d + 1) * PXH + m] = __float2half_rn(f1);
            }
            es += __shfl_xor_sync(0xffffffffu, es, 1);
            es += __shfl_xor_sync(0xffffffffu, es, 2);
            ed += __shfl_xor_sync(0xffffffffu, ed, 1);
            ed += __shfl_xor_sync(0xffffffffu, ed, 2);
            if (tg == 0) { esh[h * 128 + m] = es; edh[h * 128 + m] = ed; }
        }
    }
    __syncthreads();
    {
        int b = row0 >> 11, nloc = row0 & (Nq - 1);
        int d = tid >> 2, c = tid & 3;
        const uint4* src = (const uint4*)(xph + (size_t)d * PXH + c * 32);
        uint4* dst = (uint4*)(g_xpT + ((size_t)b * DOUT + d) * Nq + nloc + c * 32);
        #pragma unroll
        for (int i = 0; i < 4; i++) dst[i] = src[i];
    }
    if (tid < 128) {
        g_es[row0 + tid] = esh[tid] + esh[128 + tid];
        g_ed[row0 + tid] = edh[tid] + edh[128 + tid];
    }
}

// ---------------------------------------------------------------------------
// Kernel 2: warp-specialized GAT attention, direct adj, fp16 producer math.
// Per-row shift G_m = lrelu(es_m + Md0), Md0 = max_n ed -> all weights <= 1
// (fp16-safe, per-m factors cancel in softmax). Denominator computed by the
// CONSUMERS via an extra ones-B mma16 (sums exactly the fp16 P the numerator
// MMA consumes) -> producers do no dsum work, no dsh, no trailing syncs.
// ---------------------------------------------------------------------------
#define GPS_STRIDE 34816                 // 128*PITH*2 bytes
#define GXT_STRIDE 17408                 // 64*PITH*2 bytes
#define GXT_BASE   (3 * GPS_STRIDE)
#define GE1_OFF    (GXT_BASE + 3 * GXT_STRIDE)   // half[2048] exp(ed-Md0)
#define GEA_OFF    (GE1_OFF + 4096)              // half[2048] exp(.2(ed-Md0))
#define GS1_OFF    (GEA_OFF + 4096)              // uint[128] half2 dup
#define GSA_OFF    (GS1_OFF + 512)               // uint[128] half2 dup
#define GRD_OFF    (GSA_OFF + 512)               // reduction scratch (64B)
#define GA_SIZE    (GRD_OFF + 128)

__global__ void __launch_bounds__(512, 1)
k_gat(const int* __restrict__ adj, float* __restrict__ out) {
    extern __shared__ char smc[];
    __half*   E1h  = (__half*)(smc + GE1_OFF);
    __half*   EAh  = (__half*)(smc + GEA_OFF);
    uint32_t* Es1h = (uint32_t*)(smc + GS1_OFF);
    uint32_t* Esah = (uint32_t*)(smc + GSA_OFF);
    float*    red  = (float*)(smc + GRD_OFF);

    int tid = threadIdx.x, wid = tid >> 5, lid = tid & 31;
    int g = lid >> 2, tg = lid & 3;
    int b  = blockIdx.x >> 4;
    int m0 = (blockIdx.x & 15) << 7;

    // ---- Md0 = max_n ed, then fp16 tables ----
    float edv[4];
    {
        const float* edb = g_ed + b * Nq;
        float lmax = -1e30f;
        #pragma unroll
        for (int i = 0; i < 4; i++) {
            edv[i] = edb[tid + 512 * i];
            lmax = fmaxf(lmax, edv[i]);
        }
        #pragma unroll
        for (int off = 16; off; off >>= 1)
            lmax = fmaxf(lmax, __shfl_xor_sync(0xffffffffu, lmax, off));
        if (lid == 0) red[wid] = lmax;
    }
    __syncthreads();
    float Md0;
    {
        float m16 = red[tid & 15];
        #pragma unroll
        for (int off = 8; off; off >>= 1)
            m16 = fmaxf(m16, __shfl_xor_sync(0xffffffffu, m16, off));
        Md0 = m16;   // uniform across block
    }
    {
        #pragma unroll
        for (int i = 0; i < 4; i++) {
            int n = tid + 512 * i;
            float d = edv[i] - Md0;
            E1h[n] = __float2half_rn(__expf(d));
            EAh[n] = __float2half_rn(__expf(0.2f * d));
        }
        if (tid < 128) {
            float t = g_es[b * Nq + m0 + tid] + Md0;
            float G = fmaxf(t, 0.2f * t);
            __half h1 = __float2half_rn(__expf(t - G));
            __half ha = __float2half_rn(__expf(0.2f * t - G));
            uint32_t u1 = (uint32_t)__half_as_ushort(h1);
            uint32_t ua = (uint32_t)__half_as_ushort(ha);
            Es1h[tid] = u1 | (u1 << 16);
            Esah[tid] = ua | (ua << 16);
        }
    }
    __syncthreads();

    if (wid >= 8) {
        // =================== PRODUCER ===================
        int p = wid - 8;
        const int*    adjb = adj + (size_t)b * Nq * Nq + (size_t)m0 * Nq;
        const __half* gxT  = g_xpT + (size_t)b * DOUT * Nq;

        for (int t = 0; t < 16; t++) {
            int n0 = t << 7;
            int buf = t % 3;
            __half* PS = (__half*)(smc + buf * GPS_STRIDE);
            __half* XT = (__half*)(smc + GXT_BASE + buf * GXT_STRIDE);

            if (t >= 3) BAR_SYNC(4 + buf);

            // XT loads: warp-per-row, coalesced 256B rows
            uint2 xtv[8];
            #pragma unroll
            for (int ps = 0; ps < 8; ps++) {
                int row = ps * 8 + p;
                xtv[ps] = ((const uint2*)(gxT + (size_t)row * Nq + n0))[lid];
            }

            // hoisted n-side fp16 table pairs (4 n's per lane)
            uint2 e1p = *(const uint2*)(E1h + n0 + 4 * lid);
            uint2 eap = *(const uint2*)(EAh + n0 + 4 * lid);
            __half2 e1a = *(__half2*)&e1p.x, e1b = *(__half2*)&e1p.y;
            __half2 eaa = *(__half2*)&eap.x, eab = *(__half2*)&eap.y;

            #pragma unroll
            for (int it = 0; it < 16; it++) {
                int m = (it << 3) + p;
                __half2 e1m = *(__half2*)&Es1h[m];
                __half2 eam = *(__half2*)&Esah[m];
                int4 av = *(const int4*)(adjb + (size_t)m * Nq + n0 + 4 * lid);
                __half2 p01 = __hmax2(__hmul2(e1m, e1a), __hmul2(eam, eaa));
                __half2 p23 = __hmax2(__hmul2(e1m, e1b), __hmul2(eam, eab));
                uint32_t m01 = (av.x ? 0x0000FFFFu : 0u) | (av.y ? 0xFFFF0000u : 0u);
                uint32_t m23 = (av.z ? 0x0000FFFFu : 0u) | (av.w ? 0xFFFF0000u : 0u);
                uint2 pk;
                pk.x = (*(uint32_t*)&p01) & m01;
                pk.y = (*(uint32_t*)&p23) & m23;
                *(uint2*)(PS + (size_t)m * PITH + 4 * lid) = pk;
            }
            #pragma unroll
            for (int ps = 0; ps < 8; ps++) {
                int row = ps * 8 + p;
                *(uint2*)(XT + (size_t)row * PITH + 4 * lid) = xtv[ps];
            }
            BAR_ARRIVE(1 + buf);
        }
    } else {
        // =================== CONSUMER ===================
        const uint32_t HONES = 0x3C003C00u;   // half2(1,1)
        float acc[2][4][4];
        float accO[2][4];                     // ones-MMA row sums (denominators)
        #pragma unroll
        for (int mt = 0; mt < 2; mt++) {
            #pragma unroll
            for (int j = 0; j < 4; j++)
                #pragma unroll
                for (int c = 0; c < 4; c++) acc[mt][j][c] = 0.f;
            #pragma unroll
            for (int c = 0; c < 4; c++) accO[mt][c] = 0.f;
        }

        int gm = wid >> 1, dg = wid & 1;

        for (int t = 0; t < 16; t++) {
            int buf = t % 3;
            const __half* PS = (const __half*)(smc + buf * GPS_STRIDE);
            const __half* XT = (const __half*)(smc + GXT_BASE + buf * GXT_STRIDE);
            const __half* Abase = PS + (32 * gm + g) * PITH + 2 * tg;
            const __half* Bbase = XT + (32 * dg + g) * PITH + 2 * tg;

            BAR_SYNC(1 + buf);

            #pragma unroll
            for (int ks = 0; ks < 8; ks++) {
                int kb = ks * 16;
                uint32_t A[2][4];
                #pragma unroll
                for (int mt = 0; mt < 2; mt++) {
                    const __half* ap = Abase + mt * 16 * PITH + kb;
                    A[mt][0] = *(const uint32_t*)(ap);
                    A[mt][1] = *(const uint32_t*)(ap + 8 * PITH);
                    A[mt][2] = *(const uint32_t*)(ap + 8);
                    A[mt][3] = *(const uint32_t*)(ap + 8 * PITH + 8);
                }
                #pragma unroll
                for (int j = 0; j < 4; j++) {
                    const __half* bp = Bbase + j * 8 * PITH + kb;
                    uint32_t B0 = *(const uint32_t*)(bp);
                    uint32_t B1 = *(const uint32_t*)(bp + 8);
                    mma16(acc[0][j], A[0], B0, B1);
                    mma16(acc[1][j], A[1], B0, B1);
                }
                mma16(accO[0], A[0], HONES, HONES);
                mma16(accO[1], A[1], HONES, HONES);
            }
            if (t < 13) BAR_ARRIVE(4 + buf);
        }

        // ---- normalize + write (denominator held locally) ----
        float* ob = out + ((size_t)b * Nq + m0) * DOUT;
        #pragma unroll
        for (int mt = 0; mt < 2; mt++) {
            #pragma unroll
            for (int rw = 0; rw < 2; rw++) {
                int m = 32 * gm + 16 * mt + g + 8 * rw;
                float inv = 1.0f / accO[mt][2 * rw];
                #pragma unroll
                for (int j = 0; j < 4; j++) {
                    float2 o = make_float2(acc[mt][j][2 * rw] * inv,
                                           acc[mt][j][2 * rw + 1] * inv);
                    *(float2*)(ob + (size_t)m * DOUT + 32 * dg + 8 * j + 2 * tg) = o;
                }
            }
        }
    }
}

// ---------------------------------------------------------------------------
extern "C" void kernel_launch(void* const* d_in, const int* in_sizes, int n_in,
                              void* d_out, int out_size) {
    const float* x    = (const float*)d_in[0];
    const int*   adj  = (const int*)d_in[1];
    const float* W    = (const float*)d_in[2];
    const float* bvec = (const float*)d_in[3];
    const float* a    = (const float*)d_in[4];
    float* out = (float*)d_out;

    cudaFuncSetAttribute(k_proj, cudaFuncAttributeMaxDynamicSharedMemorySize, PJ_SIZE);
    cudaFuncSetAttribute(k_gat,  cudaFuncAttributeMaxDynamicSharedMemorySize, GA_SIZE);

    k_proj<<<Bq * Nq / 128, 256, PJ_SIZE>>>(x, W, bvec, a);
    k_gat<<<Bq * (Nq / 128), 512, GA_SIZE>>>(adj, out);
}

// round 17
// speedup vs baseline: 1.5354x; 1.0464x over previous
#include <cuda_runtime.h>
#include <cuda_fp16.h>
#include <cstdint>

#define Bq   8
#define Nq   2048
#define DIN  128
#define DOUT 64
#define PIT  132    // fp32 smem pitch (k_proj)
#define PITH 136    // half smem pitch (k_gat)
#define PXH  136    // half pitch for k_proj xp staging

__device__ __half g_xpT[Bq * DOUT * Nq];  // projected features, half, [b][d][n]
__device__ float  g_es[Bq * Nq];
__device__ float  g_ed[Bq * Nq];

static __device__ __forceinline__ float to_tf32(float x) {
    uint32_t r;
    asm("cvt.rna.tf32.f32 %0, %1;" : "=r"(r) : "f"(x));
    return __uint_as_float(r);
}

// tf32: D += A(16x8) * B(8x8)
static __device__ __forceinline__ void mma8(float* c, const uint32_t* a,
                                            uint32_t b0, uint32_t b1) {
    asm volatile(
        "mma.sync.aligned.m16n8k8.row.col.f32.tf32.tf32.f32 "
        "{%0,%1,%2,%3}, {%4,%5,%6,%7}, {%8,%9}, {%0,%1,%2,%3};"
        : "+f"(c[0]), "+f"(c[1]), "+f"(c[2]), "+f"(c[3])
        : "r"(a[0]), "r"(a[1]), "r"(a[2]), "r"(a[3]), "r"(b0), "r"(b1));
}
// fp16: D += A(16x16) * B(16x8), fp32 accum
static __device__ __forceinline__ void mma16(float* c, const uint32_t* a,
                                             uint32_t b0, uint32_t b1) {
    asm volatile(
        "mma.sync.aligned.m16n8k16.row.col.f32.f16.f16.f32 "
        "{%0,%1,%2,%3}, {%4,%5,%6,%7}, {%8,%9}, {%0,%1,%2,%3};"
        : "+f"(c[0]), "+f"(c[1]), "+f"(c[2]), "+f"(c[3])
        : "r"(a[0]), "r"(a[1]), "r"(a[2]), "r"(a[3]), "r"(b0), "r"(b1));
}

#define BAR_SYNC(id)   asm volatile("bar.sync %0, 512;"   :: "r"(id) : "memory")
#define BAR_ARRIVE(id) asm volatile("bar.arrive %0, 512;" :: "r"(id) : "memory")

// ---------------------------------------------------------------------------
// Kernel 1: xp = x @ W^T + b via tf32 mma.sync (unchanged from R14/R16).
// ---------------------------------------------------------------------------
#define PJ_AS   0
#define PJ_WS   (128 * PIT)
#define PJ_BS   (PJ_WS + 64 * PIT)
#define PJ_ASR  (PJ_BS + 64)
#define PJ_ADR  (PJ_ASR + 64)
#define PJ_ESH  (PJ_ADR + 64)
#define PJ_EDH  (PJ_ESH + 256)
#define PJ_XPH  (PJ_EDH + 256)
#define PJ_SIZE ((PJ_XPH + 32 * PXH) * 4)

__global__ void __launch_bounds__(256, 1)
k_proj(const float* __restrict__ x, const float* __restrict__ W,
       const float* __restrict__ bvec, const float* __restrict__ a) {
    extern __shared__ float sh[];
    float* AS  = sh + PJ_AS;
    float* WS  = sh + PJ_WS;
    float* bsh = sh + PJ_BS;
    float* asr = sh + PJ_ASR;
    float* adr = sh + PJ_ADR;
    float* esh = sh + PJ_ESH;
    float* edh = sh + PJ_EDH;
    __half* xph = (__half*)(sh + PJ_XPH);

    int tid = threadIdx.x, wid = tid >> 5, lid = tid & 31;
    int g = lid >> 2, tg = lid & 3;
    int row0 = blockIdx.x << 7;

    {
        int r = tid & 127, half = tid >> 7;
        const float4* src = (const float4*)(x + (size_t)(row0 + r) * DIN + half * 64);
        float* dst = AS + r * PIT + half * 64;
        #pragma unroll
        for (int i = 0; i < 16; i++) {
            float4 v = src[i];
            v.x = to_tf32(v.x); v.y = to_tf32(v.y);
            v.z = to_tf32(v.z); v.w = to_tf32(v.w);
            ((float4*)dst)[i] = v;
        }
    }
    {
        int d = tid & 63, q = tid >> 6;
        const float4* src = (const float4*)(W + (size_t)d * DIN + q * 32);
        float* dst = WS + d * PIT + q * 32;
        #pragma unroll
        for (int i = 0; i < 8; i++) {
            float4 v = src[i];
            v.x = to_tf32(v.x); v.y = to_tf32(v.y);
            v.z = to_tf32(v.z); v.w = to_tf32(v.w);
            ((float4*)dst)[i] = v;
        }
    }
    if (tid < 64) {
        bsh[tid] = bvec[tid];
        asr[tid] = a[tid];
        adr[tid] = a[DOUT + tid];
    }
    __syncthreads();

    float acc[2][4][4];
    #pragma unroll
    for (int t = 0; t < 2; t++)
        #pragma unroll
        for (int j = 0; j < 4; j++)
            #pragma unroll
            for (int c = 0; c < 4; c++) acc[t][j][c] = 0.f;

    int gm = wid >> 1, h = wid & 1;
    const float* Abase = AS + (32 * gm + g) * PIT + tg;
    const float* Bbase = WS + (32 * h + g) * PIT + tg;

    #pragma unroll
    for (int ks = 0; ks < 16; ks++) {
        int kb = ks * 8;
        uint32_t A[2][4];
        #pragma unroll
        for (int t = 0; t < 2; t++) {
            const float* ap = Abase + t * 16 * PIT + kb;
            A[t][0] = __float_as_uint(ap[0]);
            A[t][1] = __float_as_uint(ap[8 * PIT]);
            A[t][2] = __float_as_uint(ap[4]);
            A[t][3] = __float_as_uint(ap[8 * PIT + 4]);
        }
        #pragma unroll
        for (int j = 0; j < 4; j++) {
            const float* bp = Bbase + j * 8 * PIT + kb;
            uint32_t B0 = __float_as_uint(bp[0]);
            uint32_t B1 = __float_as_uint(bp[4]);
            mma8(acc[0][j], A[0], B0, B1);
            mma8(acc[1][j], A[1], B0, B1);
        }
    }

    #pragma unroll
    for (int t = 0; t < 2; t++) {
        #pragma unroll
        for (int rw = 0; rw < 2; rw++) {
            int m = 32 * gm + g + 16 * t + 8 * rw;
            float es = 0.f, ed = 0.f;
            #pragma unroll
            for (int j = 0; j < 4; j++) {
                int d = 32 * h + 8 * j + 2 * tg;
                float f0 = acc[t][j][2 * rw]     + bsh[d];
                float f1 = acc[t][j][2 * rw + 1] + bsh[d + 1];
                es += f0 * asr[d] + f1 * asr[d + 1];
                ed += f0 * adr[d] + f1 * adr[d + 1];
                xph[(size_t)d * PXH + m]       = __float2half_rn(f0);
                xph[(size_t)(d + 1) * PXH + m] = __float2half_rn(f1);
            }
            es += __shfl_xor_sync(0xffffffffu, es, 1);
            es += __shfl_xor_sync(0xffffffffu, es, 2);
            ed += __shfl_xor_sync(0xffffffffu, ed, 1);
            ed += __shfl_xor_sync(0xffffffffu, ed, 2);
            if (tg == 0) { esh[h * 128 + m] = es; edh[h * 128 + m] = ed; }
        }
    }
    __syncthreads();
    {
        int b = row0 >> 11, nloc = row0 & (Nq - 1);
        int d = tid >> 2, c = tid & 3;
        const uint4* src = (const uint4*)(xph + (size_t)d * PXH + c * 32);
        uint4* dst = (uint4*)(g_xpT + ((size_t)b * DOUT + d) * Nq + nloc + c * 32);
        #pragma unroll
        for (int i = 0; i < 4; i++) dst[i] = src[i];
    }
    if (tid < 128) {
        g_es[row0 + tid] = esh[tid] + esh[128 + tid];
        g_ed[row0 + tid] = edh[tid] + edh[128 + tid];
    }
}

// ---------------------------------------------------------------------------
// Kernel 2: R16 winner + two latency levers:
//  - L2 prefetch of tile t+1's adj lines (zero registers)
//  - 4-deep P/XT ring (one more tile of producer run-ahead)
// fp16 producer math, ones-MMA denominators, direct adj.
// ---------------------------------------------------------------------------
#define NBUF       4
#define GPS_STRIDE 34816                 // 128*PITH*2 bytes
#define GXT_STRIDE 17408                 // 64*PITH*2 bytes
#define GXT_BASE   (NBUF * GPS_STRIDE)                 // 139264
#define GE1_OFF    (GXT_BASE + NBUF * GXT_STRIDE)      // 208896
#define GEA_OFF    (GE1_OFF + 4096)
#define GS1_OFF    (GEA_OFF + 4096)
#define GSA_OFF    (GS1_OFF + 512)
#define GRD_OFF    (GSA_OFF + 512)
#define GA_SIZE    (GRD_OFF + 128)       // 218240 (~213KB)

__global__ void __launch_bounds__(512, 1)
k_gat(const int* __restrict__ adj, float* __restrict__ out) {
    extern __shared__ char smc[];
    __half*   E1h  = (__half*)(smc + GE1_OFF);
    __half*   EAh  = (__half*)(smc + GEA_OFF);
    uint32_t* Es1h = (uint32_t*)(smc + GS1_OFF);
    uint32_t* Esah = (uint32_t*)(smc + GSA_OFF);
    float*    red  = (float*)(smc + GRD_OFF);

    int tid = threadIdx.x, wid = tid >> 5, lid = tid & 31;
    int g = lid >> 2, tg = lid & 3;
    int b  = blockIdx.x >> 4;
    int m0 = (blockIdx.x & 15) << 7;

    // ---- Md0 = max_n ed, then fp16 tables ----
    float edv[4];
    {
        const float* edb = g_ed + b * Nq;
        float lmax = -1e30f;
        #pragma unroll
        for (int i = 0; i < 4; i++) {
            edv[i] = edb[tid + 512 * i];
            lmax = fmaxf(lmax, edv[i]);
        }
        #pragma unroll
        for (int off = 16; off; off >>= 1)
            lmax = fmaxf(lmax, __shfl_xor_sync(0xffffffffu, lmax, off));
        if (lid == 0) red[wid] = lmax;
    }
    __syncthreads();
    float Md0;
    {
        float m16 = red[tid & 15];
        #pragma unroll
        for (int off = 8; off; off >>= 1)
            m16 = fmaxf(m16, __shfl_xor_sync(0xffffffffu, m16, off));
        Md0 = m16;   // uniform across block
    }
    {
        #pragma unroll
        for (int i = 0; i < 4; i++) {
            int n = tid + 512 * i;
            float d = edv[i] - Md0;
            E1h[n] = __float2half_rn(__expf(d));
            EAh[n] = __float2half_rn(__expf(0.2f * d));
        }
        if (tid < 128) {
            float t = g_es[b * Nq + m0 + tid] + Md0;
            float G = fmaxf(t, 0.2f * t);
            __half h1 = __float2half_rn(__expf(t - G));
            __half ha = __float2half_rn(__expf(0.2f * t - G));
            uint32_t u1 = (uint32_t)__half_as_ushort(h1);
            uint32_t ua = (uint32_t)__half_as_ushort(ha);
            Es1h[tid] = u1 | (u1 << 16);
            Esah[tid] = ua | (ua << 16);
        }
    }
    __syncthreads();

    if (wid >= 8) {
        // =================== PRODUCER ===================
        int p = wid - 8;
        const int*    adjb = adj + (size_t)b * Nq * Nq + (size_t)m0 * Nq;
        const __half* gxT  = g_xpT + (size_t)b * DOUT * Nq;
        bool pfl = ((lid & 7) == 0);        // lanes 0,8,16,24: one per 128B line

        for (int t = 0; t < 16; t++) {
            int n0 = t << 7;
            int buf = t & (NBUF - 1);
            __half* PS = (__half*)(smc + buf * GPS_STRIDE);
            __half* XT = (__half*)(smc + GXT_BASE + buf * GXT_STRIDE);

            if (t >= NBUF) BAR_SYNC(5 + buf);

            // XT loads: warp-per-row, coalesced 256B rows
            uint2 xtv[8];
            #pragma unroll
            for (int ps = 0; ps < 8; ps++) {
                int row = ps * 8 + p;
                xtv[ps] = ((const uint2*)(gxT + (size_t)row * Nq + n0))[lid];
            }

            // L2 prefetch of next tile's adj lines (no regs, no deps)
            if (t < 15 && pfl) {
                int n1 = n0 + 128;
                #pragma unroll
                for (int it = 0; it < 16; it++) {
                    const int* pa = adjb + (size_t)((it << 3) + p) * Nq + n1 + 4 * lid;
                    asm volatile("prefetch.global.L2 [%0];" :: "l"(pa));
                }
            }

            // hoisted n-side fp16 table pairs (4 n's per lane)
            uint2 e1p = *(const uint2*)(E1h + n0 + 4 * lid);
            uint2 eap = *(const uint2*)(EAh + n0 + 4 * lid);
            __half2 e1a = *(__half2*)&e1p.x, e1b = *(__half2*)&e1p.y;
            __half2 eaa = *(__half2*)&eap.x, eab = *(__half2*)&eap.y;

            #pragma unroll
            for (int it = 0; it < 16; it++) {
                int m = (it << 3) + p;
                __half2 e1m = *(__half2*)&Es1h[m];
                __half2 eam = *(__half2*)&Esah[m];
                int4 av = *(const int4*)(adjb + (size_t)m * Nq + n0 + 4 * lid);
                __half2 p01 = __hmax2(__hmul2(e1m, e1a), __hmul2(eam, eaa));
                __half2 p23 = __hmax2(__hmul2(e1m, e1b), __hmul2(eam, eab));
                uint32_t m01 = (av.x ? 0x0000FFFFu : 0u) | (av.y ? 0xFFFF0000u : 0u);
                uint32_t m23 = (av.z ? 0x0000FFFFu : 0u) | (av.w ? 0xFFFF0000u : 0u);
                uint2 pk;
                pk.x = (*(uint32_t*)&p01) & m01;
                pk.y = (*(uint32_t*)&p23) & m23;
                *(uint2*)(PS + (size_t)m * PITH + 4 * lid) = pk;
            }
            #pragma unroll
            for (int ps = 0; ps < 8; ps++) {
                int row = ps * 8 + p;
                *(uint2*)(XT + (size_t)row * PITH + 4 * lid) = xtv[ps];
            }
            BAR_ARRIVE(1 + buf);
        }
    } else {
        // =================== CONSUMER ===================
        const uint32_t HONES = 0x3C003C00u;   // half2(1,1)
        float acc[2][4][4];
        float accO[2][4];                     // ones-MMA row sums (denominators)
        #pragma unroll
        for (int mt = 0; mt < 2; mt++) {
            #pragma unroll
            for (int j = 0; j < 4; j++)
                #pragma unroll
                for (int c = 0; c < 4; c++) acc[mt][j][c] = 0.f;
            #pragma unroll
            for (int c = 0; c < 4; c++) accO[mt][c] = 0.f;
        }

        int gm = wid >> 1, dg = wid & 1;

        for (int t = 0; t < 16; t++) {
            int buf = t & (NBUF - 1);
            const __half* PS = (const __half*)(smc + buf * GPS_STRIDE);
            const __half* XT = (const __half*)(smc + GXT_BASE + buf * GXT_STRIDE);
            const __half* Abase = PS + (32 * gm + g) * PITH + 2 * tg;
            const __half* Bbase = XT + (32 * dg + g) * PITH + 2 * tg;

            BAR_SYNC(1 + buf);

            #pragma unroll
            for (int ks = 0; ks < 8; ks++) {
                int kb = ks * 16;
                uint32_t A[2][4];
                #pragma unroll
                for (int mt = 0; mt < 2; mt++) {
                    const __half* ap = Abase + mt * 16 * PITH + kb;
                    A[mt][0] = *(const uint32_t*)(ap);
                    A[mt][1] = *(const uint32_t*)(ap + 8 * PITH);
                    A[mt][2] = *(const uint32_t*)(ap + 8);
                    A[mt][3] = *(const uint32_t*)(ap + 8 * PITH + 8);
                }
                #pragma unroll
                for (int j = 0; j < 4; j++) {
                    const __half* bp = Bbase + j * 8 * PITH + kb;
                    uint32_t B0 = *(const uint32_t*)(bp);
                    uint32_t B1 = *(const uint32_t*)(bp + 8);
                    mma16(acc[0][j], A[0], B0, B1);
                    mma16(acc[1][j], A[1], B0, B1);
                }
                mma16(accO[0], A[0], HONES, HONES);
                mma16(accO[1], A[1], HONES, HONES);
            }
            if (t < 16 - NBUF) BAR_ARRIVE(5 + buf);
        }

        // ---- normalize + write (denominator held locally) ----
        float* ob = out + ((size_t)b * Nq + m0) * DOUT;
        #pragma unroll
        for (int mt = 0; mt < 2; mt++) {
            #pragma unroll
            for (int rw = 0; rw < 2; rw++) {
                int m = 32 * gm + 16 * mt + g + 8 * rw;
                float inv = 1.0f / accO[mt][2 * rw];
                #pragma unroll
                for (int j = 0; j < 4; j++) {
                    float2 o = make_float2(acc[mt][j][2 * rw] * inv,
                                           acc[mt][j][2 * rw + 1] * inv);
                    *(float2*)(ob + (size_t)m * DOUT + 32 * dg + 8 * j + 2 * tg) = o;
                }
            }
        }
    }
}

// ---------------------------------------------------------------------------
extern "C" void kernel_launch(void* const* d_in, const int* in_sizes, int n_in,
                              void* d_out, int out_size) {
    const float* x    = (const float*)d_in[0];
    const int*   adj  = (const int*)d_in[1];
    const float* W    = (const float*)d_in[2];
    const float* bvec = (const float*)d_in[3];
    const float* a    = (const float*)d_in[4];
    float* out = (float*)d_out;

    cudaFuncSetAttribute(k_proj, cudaFuncAttributeMaxDynamicSharedMemorySize, PJ_SIZE);
    cudaFuncSetAttribute(k_gat,  cudaFuncAttributeMaxDynamicSharedMemorySize, GA_SIZE);

    k_proj<<<Bq * Nq / 128, 256, PJ_SIZE>>>(x, W, bvec, a);
    k_gat<<<Bq * (Nq / 128), 512, GA_SIZE>>>(adj, out);
}